// round 16
// baseline (speedup 1.0000x reference)
#include <cuda_runtime.h>
#include <cuda_bf16.h>
#include <stdint.h>

#define Tlen 96
#define NTH  512

// Pre-swizzled bf16 hi/lo tiles in device scratch (L2-resident).
// Wg : [cb][gate(r,z,n)][hl][chunk<10] {64n x 64k}  (chunks 0-7 = w_hh k, 8-9 = w_ih k)
// Wf : [cb][hl][chunk<8] {16n x 64k}
// Act: [buf][mb][hl][chunk<10] {128m x 64k}         (chunks 0-7 = h, 8-9 = x)
__device__ __align__(16) __nv_bfloat16 d_Wg[8][3][2][10][4096];
__device__ __align__(16) __nv_bfloat16 d_Wf[8][2][8][1024];
__device__ __align__(16) __nv_bfloat16 d_Act[2][16][2][10][8192];
__device__ unsigned int d_bar;

// Tile layout: row-major rows of 64 bf16 (128B), 16B units xor-swizzled by row
// (unit' = unit ^ (row&7)) so ldmatrix is bank-conflict-free.
__host__ __device__ __forceinline__ int tile_off(int row, int kk) {
    int unit = (kk >> 3) ^ (row & 7);
    return row * 128 + (unit << 4) + (kk & 7) * 2;
}
__device__ __forceinline__ void bsplit(float f, __nv_bfloat16& hi, __nv_bfloat16& lo) {
    hi = __float2bfloat16(f);
    lo = __float2bfloat16(f - __bfloat162float(hi));
}
__device__ __forceinline__ uint32_t smem_u32(const void* p) {
    uint32_t a;
    asm("{ .reg .u64 t; cvta.to.shared.u64 t, %1; cvt.u32.u64 %0, t; }" : "=r"(a) : "l"(p));
    return a;
}
__device__ __forceinline__ void cpa16(uint32_t dst, const void* src) {
    asm volatile("cp.async.cg.shared.global [%0], [%1], 16;" :: "r"(dst), "l"(src));
}
#define CP_COMMIT() asm volatile("cp.async.commit_group;" ::: "memory")
#define CP_WAIT1()  asm volatile("cp.async.wait_group 1;" ::: "memory")
#define CP_WAIT0()  asm volatile("cp.async.wait_group 0;" ::: "memory")

__device__ __forceinline__ void ldsm4(uint32_t* r, uint32_t a) {
    asm volatile("ldmatrix.sync.aligned.m8n8.x4.shared.b16 {%0,%1,%2,%3}, [%4];"
        : "=r"(r[0]), "=r"(r[1]), "=r"(r[2]), "=r"(r[3]) : "r"(a));
}
__device__ __forceinline__ void mmabf(float* d, const uint32_t* a, const uint32_t* b) {
    asm volatile("mma.sync.aligned.m16n8k16.row.col.f32.bf16.bf16.f32 "
        "{%0,%1,%2,%3},{%4,%5,%6,%7},{%8,%9},{%0,%1,%2,%3};"
        : "+f"(d[0]), "+f"(d[1]), "+f"(d[2]), "+f"(d[3])
        : "r"(a[0]), "r"(a[1]), "r"(a[2]), "r"(a[3]), "r"(b[0]), "r"(b[1]));
}
// A fragment (m16 x k16): regs (m0-7,k0-7),(m8-15,k0-7),(m0-7,k8-15),(m8-15,k8-15)
__device__ __forceinline__ uint32_t a_addr(uint32_t base, int mrow, int q, int lane) {
    int row = mrow + ((lane >> 3) & 1) * 8 + (lane & 7);
    int unit = 2 * q + (lane >> 4);
    return base + row * 128 + ((unit ^ (row & 7)) << 4);
}
// B fragments: one x4 covers 2 n8 tiles x k16.
__device__ __forceinline__ uint32_t b_addr(uint32_t base, int nbase, int q, int lane) {
    int nrow = nbase + ((lane >> 4) << 3) + (lane & 7);
    int unit = 2 * q + ((lane >> 3) & 1);
    return base + nrow * 128 + ((unit ^ (nrow & 7)) << 4);
}

__device__ __forceinline__ float sigm(float x) { return __fdividef(1.f, 1.f + __expf(-x)); }
__device__ __forceinline__ float ftanh(float x) {
    float t = __expf(2.f * x);
    return 1.f - __fdividef(2.f, t + 1.f);
}
__device__ __forceinline__ void grid_sync(unsigned tgt) {
    __threadfence();
    __syncthreads();
    if (threadIdx.x == 0) {
        atomicAdd(&d_bar, 1u);
        while (((volatile unsigned int*)&d_bar)[0] < tgt) __nanosleep(32);
    }
    __syncthreads();
    __threadfence();
}

// ---------------- setup kernels ----------------
__global__ void setup_weights(const float* __restrict__ w_ih,
                              const float* __restrict__ w_hh,
                              const float* __restrict__ fc_w) {
    const int N1 = 8 * 3 * 10 * 4096, N2 = 8 * 8 * 1024;
    for (int idx = blockIdx.x * blockDim.x + threadIdx.x; idx < N1 + N2;
         idx += gridDim.x * blockDim.x) {
        if (idx < N1) {
            int cb = idx / (3 * 10 * 4096), r = idx % (3 * 10 * 4096);
            int g = r / (10 * 4096); r %= 10 * 4096;
            int c = r / 4096, e = r % 4096;
            int j = e >> 6, kk = e & 63;
            int n = g * 512 + cb * 64 + j;
            float f = (c < 8) ? w_hh[n * 512 + c * 64 + kk]
                              : w_ih[n * 128 + (c - 8) * 64 + kk];
            __nv_bfloat16 hi, lo; bsplit(f, hi, lo);
            int to = tile_off(j, kk);
            *(__nv_bfloat16*)((char*)&d_Wg[cb][g][0][c][0] + to) = hi;
            *(__nv_bfloat16*)((char*)&d_Wg[cb][g][1][c][0] + to) = lo;
        } else {
            int i2 = idx - N1;
            int cb = i2 / (8 * 1024), r = i2 % (8 * 1024);
            int c = r / 1024, e = r % 1024;
            int j = e >> 6, kk = e & 63;
            float f = fc_w[(cb * 16 + j) * 512 + c * 64 + kk];
            __nv_bfloat16 hi, lo; bsplit(f, hi, lo);
            int to = tile_off(j, kk);
            *(__nv_bfloat16*)((char*)&d_Wf[cb][0][c][0] + to) = hi;
            *(__nv_bfloat16*)((char*)&d_Wf[cb][1][c][0] + to) = lo;
        }
    }
}

__global__ void setup_state(const float* __restrict__ hidden) {
    const int N1 = 2048 * 512, N2 = 16 * 2 * 2 * 8192;
    for (int idx = blockIdx.x * blockDim.x + threadIdx.x; idx < N1 + N2;
         idx += gridDim.x * blockDim.x) {
        if (idx < N1) {
            int row = idx >> 9, col = idx & 511;
            int mb = row >> 7, m = row & 127, c = col >> 6, kk = col & 63;
            __nv_bfloat16 hi, lo; bsplit(hidden[idx], hi, lo);
            int to = tile_off(m, kk);
            *(__nv_bfloat16*)((char*)&d_Act[0][mb][0][c][0] + to) = hi;
            *(__nv_bfloat16*)((char*)&d_Act[0][mb][1][c][0] + to) = lo;
        } else {
            int i2 = idx - N1;
            int mb = i2 / (2 * 2 * 8192), r = i2 % (2 * 2 * 8192);
            int hl = r / (2 * 8192); r %= 2 * 8192;
            int c8 = r / 8192, e = r % 8192;
            d_Act[0][mb][hl][8 + c8][e] = __float2bfloat16(0.f);
        }
    }
    if (blockIdx.x == 0 && threadIdx.x == 0) d_bar = 0;
}

// ---------------- main persistent kernel ----------------
// smem: [64..1216) biases; A bufs @2048 (2 x 32KB); B bufs @67584 (2 x 48KB).
#define SM_A  2048
#define SM_B  67584
#define SMTOT 165888

// One gate's n16 slice for one k16: 3-product mma into acc[2][2][4].
__device__ __forceinline__ void process_gate(
    uint32_t Bg, int lane, int wn16, int q,
    const uint32_t ah[2][4], const uint32_t al[2][4], float (*acc)[2][4])
{
    uint32_t bh4[4], bl4[4];
    ldsm4(bh4, b_addr(Bg, wn16, q, lane));          // hi: 2 n8 tiles
    ldsm4(bl4, b_addr(Bg + 8192, wn16, q, lane));   // lo
    #pragma unroll
    for (int mb2 = 0; mb2 < 2; ++mb2) {
        mmabf(acc[mb2][0], ah[mb2], bh4);  mmabf(acc[mb2][1], ah[mb2], bh4 + 2);
        mmabf(acc[mb2][0], al[mb2], bh4);  mmabf(acc[mb2][1], al[mb2], bh4 + 2);
        mmabf(acc[mb2][0], ah[mb2], bl4);  mmabf(acc[mb2][1], ah[mb2], bl4 + 2);
    }
}

__global__ __launch_bounds__(NTH, 1)
void gru_main(const float* __restrict__ b_ih, const float* __restrict__ b_hh,
              const float* __restrict__ fc_b, float* __restrict__ out) {
    extern __shared__ char sm[];
    const uint32_t smb = smem_u32(sm);
    const int tid = threadIdx.x;
    const int wid = tid >> 5, lane = tid & 31;
    const int mb = blockIdx.x >> 3, cb = blockIdx.x & 7;
    const int wm32 = (wid & 3) * 32;   // warp m-rows (gates)
    const int wn16 = (wid >> 2) * 16;  // warp gate-cols (gates)

    float* s_br = (float*)(sm + 64);
    float* s_bz = s_br + 64;
    float* s_bi = s_bz + 64;
    float* s_bh = s_bi + 64;
    float* s_fb = s_bh + 64;
    if (tid < 64) {
        s_br[tid] = b_ih[cb * 64 + tid] + b_hh[cb * 64 + tid];
        s_bz[tid] = b_ih[512 + cb * 64 + tid] + b_hh[512 + cb * 64 + tid];
        s_bi[tid] = b_ih[1024 + cb * 64 + tid];
        s_bh[tid] = b_hh[1024 + cb * 64 + tid];
    }
    if (tid < 16) s_fb[tid] = fc_b[cb * 16 + tid];
    __syncthreads();

    unsigned tgt = 0;

    for (int s = 0; s < Tlen; ++s) {
        const int cur = s & 1, nxt = cur ^ 1;

        // ===== gates: [128 x (r64|z64|n64)] over K=640, 10 chunks, dbl-buffered =====
        float aR[2][2][4], aZ[2][2][4], aN[2][2][4], aI[2][2][4];
        #pragma unroll
        for (int i = 0; i < 2; ++i)
            #pragma unroll
            for (int t = 0; t < 2; ++t)
                #pragma unroll
                for (int k = 0; k < 4; ++k) {
                    aR[i][t][k] = 0.f; aZ[i][t][k] = 0.f;
                    aN[i][t][k] = 0.f; aI[i][t][k] = 0.f;
                }

        #define STAGE_GATE(c, b) do {                                              \
            const char* Ah_ = (const char*)&d_Act[cur][mb][0][(c)][0];             \
            const char* Al_ = (const char*)&d_Act[cur][mb][1][(c)][0];             \
            uint32_t AB_ = smb + SM_A + (b) * 32768;                               \
            _Pragma("unroll")                                                      \
            for (int r_ = 0; r_ < 2; ++r_) {                                       \
                int u_ = tid + r_ * NTH;                                           \
                cpa16(AB_ + u_ * 16, Ah_ + u_ * 16);                               \
                cpa16(AB_ + 16384 + u_ * 16, Al_ + u_ * 16);                       \
            }                                                                      \
            uint32_t BB_ = smb + SM_B + (b) * 49152;                               \
            _Pragma("unroll")                                                      \
            for (int r_ = 0; r_ < 6; ++r_) {                                       \
                int u_ = tid + r_ * NTH;           /* 0..3071 */                   \
                int t_ = u_ >> 9, e_ = u_ & 511;                                   \
                const char* src_ = (const char*)&d_Wg[cb][t_ >> 1][t_ & 1][(c)][0];\
                uint32_t dst_ = BB_ + (t_ >> 1) * 16384 + (t_ & 1) * 8192;         \
                cpa16(dst_ + e_ * 16, src_ + e_ * 16);                             \
            }                                                                      \
        } while (0)

        STAGE_GATE(0, 0);
        CP_COMMIT();
        #pragma unroll 1
        for (int c = 0; c < 10; ++c) {
            if (c < 9) { STAGE_GATE(c + 1, (c + 1) & 1); CP_COMMIT(); CP_WAIT1(); }
            else       { CP_WAIT0(); }
            __syncthreads();
            const uint32_t AB = smb + SM_A + (c & 1) * 32768;
            const uint32_t BB = smb + SM_B + (c & 1) * 49152;
            float (*aX)[2][4] = (c < 8) ? aN : aI;
            #pragma unroll
            for (int q = 0; q < 4; ++q) {
                uint32_t ah[2][4], al[2][4];
                ldsm4(ah[0], a_addr(AB, wm32, q, lane));
                ldsm4(ah[1], a_addr(AB, wm32 + 16, q, lane));
                ldsm4(al[0], a_addr(AB + 16384, wm32, q, lane));
                ldsm4(al[1], a_addr(AB + 16384, wm32 + 16, q, lane));
                process_gate(BB,         lane, wn16, q, ah, al, aR);
                process_gate(BB + 16384, lane, wn16, q, ah, al, aZ);
                process_gate(BB + 32768, lane, wn16, q, ah, al, aX);
            }
            __syncthreads();
        }

        // ===== gates epilogue: h_new for cols cb*64 + [0,64) (register-local) =====
        {
            const char* hiC = (const char*)&d_Act[cur][mb][0][cb][0];
            const char* loC = (const char*)&d_Act[cur][mb][1][cb][0];
            char* hiN = (char*)&d_Act[nxt][mb][0][cb][0];
            char* loN = (char*)&d_Act[nxt][mb][1][cb][0];
            #pragma unroll
            for (int mb2 = 0; mb2 < 2; ++mb2)
                #pragma unroll
                for (int nt = 0; nt < 2; ++nt) {
                    const int jj = wn16 + nt * 8 + 2 * (lane & 3);
                    #pragma unroll
                    for (int ms = 0; ms < 2; ++ms) {
                        const int m_ = wm32 + mb2 * 16 + (lane >> 2) + ms * 8;
                        const int eo = tile_off(m_, jj);
                        __nv_bfloat162 oh = *(const __nv_bfloat162*)(hiC + eo);
                        __nv_bfloat162 ol = *(const __nv_bfloat162*)(loC + eo);
                        float hp0 = __bfloat162float(oh.x) + __bfloat162float(ol.x);
                        float hp1 = __bfloat162float(oh.y) + __bfloat162float(ol.y);
                        float r0 = sigm(aR[mb2][nt][ms * 2]     + s_br[jj]);
                        float r1 = sigm(aR[mb2][nt][ms * 2 + 1] + s_br[jj + 1]);
                        float z0 = sigm(aZ[mb2][nt][ms * 2]     + s_bz[jj]);
                        float z1 = sigm(aZ[mb2][nt][ms * 2 + 1] + s_bz[jj + 1]);
                        float n0 = ftanh(aI[mb2][nt][ms * 2]     + s_bi[jj] +
                                         r0 * (aN[mb2][nt][ms * 2]     + s_bh[jj]));
                        float n1 = ftanh(aI[mb2][nt][ms * 2 + 1] + s_bi[jj + 1] +
                                         r1 * (aN[mb2][nt][ms * 2 + 1] + s_bh[jj + 1]));
                        float h0 = (1.f - z0) * n0 + z0 * hp0;
                        float h1 = (1.f - z1) * n1 + z1 * hp1;
                        __nv_bfloat16 q0, l0, q1, l1;
                        bsplit(h0, q0, l0); bsplit(h1, q1, l1);
                        __nv_bfloat162 vh; vh.x = q0; vh.y = q1;
                        __nv_bfloat162 vl; vl.x = l0; vl.y = l1;
                        *(__nv_bfloat162*)(hiN + eo) = vh;
                        *(__nv_bfloat162*)(loN + eo) = vl;
                    }
                }
        }
        tgt += 128;
        grid_sync(tgt);   // all h_new tiles visible

        // ===== fc: [128 x 16] over K=512 (h_new), 8 chunks, dbl-buffered =====
        // 16 warps: 8 m-groups (m16) x 2 n-groups (n8)
        const int fmg = wid >> 1, fng = wid & 1;
        float f0[4];
        #pragma unroll
        for (int k = 0; k < 4; ++k) f0[k] = 0.f;

        #define STAGE_FC(c, b) do {                                                \
            const char* Ah_ = (const char*)&d_Act[nxt][mb][0][(c)][0];             \
            const char* Al_ = (const char*)&d_Act[nxt][mb][1][(c)][0];             \
            uint32_t AB_ = smb + SM_A + (b) * 32768;                               \
            _Pragma("unroll")                                                      \
            for (int r_ = 0; r_ < 2; ++r_) {                                       \
                int u_ = tid + r_ * NTH;                                           \
                cpa16(AB_ + u_ * 16, Ah_ + u_ * 16);                               \
                cpa16(AB_ + 16384 + u_ * 16, Al_ + u_ * 16);                       \
            }                                                                      \
            uint32_t BB_ = smb + SM_B + (b) * 49152;                               \
            if (tid < 256) {                                                       \
                int t_ = tid >> 7, u_ = tid & 127;                                 \
                const char* src_ = (const char*)&d_Wf[cb][t_][(c)][0];             \
                cpa16(BB_ + t_ * 2048 + u_ * 16, src_ + u_ * 16);                  \
            }                                                                      \
        } while (0)

        STAGE_FC(0, 0);
        CP_COMMIT();
        #pragma unroll 1
        for (int c = 0; c < 8; ++c) {
            if (c < 7) { STAGE_FC(c + 1, (c + 1) & 1); CP_COMMIT(); CP_WAIT1(); }
            else       { CP_WAIT0(); }
            __syncthreads();
            const uint32_t AB = smb + SM_A + (c & 1) * 32768;
            const uint32_t BB = smb + SM_B + (c & 1) * 49152;
            #pragma unroll
            for (int q = 0; q < 4; ++q) {
                uint32_t ah[4], al[4], bh4[4], bl4[4];
                ldsm4(ah, a_addr(AB, fmg * 16, q, lane));
                ldsm4(al, a_addr(AB + 16384, fmg * 16, q, lane));
                ldsm4(bh4, b_addr(BB, 0, q, lane));          // hi: 2 n8 tiles
                ldsm4(bl4, b_addr(BB + 2048, 0, q, lane));   // lo
                mmabf(f0, ah, bh4 + 2 * fng);
                mmabf(f0, al, bh4 + 2 * fng);
                mmabf(f0, ah, bl4 + 2 * fng);
            }
            __syncthreads();
        }

        // ===== fc epilogue: x_new cols cb*16+[0,16) -> out + x tiles =====
        {
            const int trow = Tlen - 1 - s;   // reference reverses time at the end
            const int xc = 8 + (cb >> 2);
            char* xhi = (char*)&d_Act[nxt][mb][0][xc][0];
            char* xlo = (char*)&d_Act[nxt][mb][1][xc][0];
            const int col = fng * 8 + 2 * (lane & 3);
            #pragma unroll
            for (int ms = 0; ms < 2; ++ms) {
                const int m_ = fmg * 16 + (lane >> 2) + ms * 8;
                float x0 = f0[ms * 2]     + s_fb[col];
                float x1 = f0[ms * 2 + 1] + s_fb[col + 1];
                *(float2*)&out[((size_t)(mb * 128 + m_) * Tlen + trow) * 128 +
                               cb * 16 + col] = make_float2(x0, x1);
                const int kk = (cb & 3) * 16 + col;
                const int eo = tile_off(m_, kk);
                __nv_bfloat16 q0, l0, q1, l1;
                bsplit(x0, q0, l0); bsplit(x1, q1, l1);
                __nv_bfloat162 vh; vh.x = q0; vh.y = q1;
                __nv_bfloat162 vl; vl.x = l0; vl.y = l1;
                *(__nv_bfloat162*)(xhi + eo) = vh;
                *(__nv_bfloat162*)(xlo + eo) = vl;
            }
        }
        tgt += 128;
        grid_sync(tgt);   // x tiles visible before next step
    }
}

extern "C" void kernel_launch(void* const* d_in, const int* in_sizes, int n_in,
                              void* d_out, int out_size) {
    const float* hidden = (const float*)d_in[0];
    const float* w_ih   = (const float*)d_in[1];
    const float* w_hh   = (const float*)d_in[2];
    const float* b_ih   = (const float*)d_in[3];
    const float* b_hh   = (const float*)d_in[4];
    const float* fc_w   = (const float*)d_in[5];
    const float* fc_b   = (const float*)d_in[6];
    float* out = (float*)d_out;

    setup_weights<<<1024, 256>>>(w_ih, w_hh, fc_w);
    setup_state<<<1024, 256>>>(hidden);

    cudaFuncSetAttribute(gru_main, cudaFuncAttributeMaxDynamicSharedMemorySize, SMTOT);
    gru_main<<<128, NTH, SMTOT>>>(b_ih, b_hh, fc_b, out);
}

// round 17
// speedup vs baseline: 1.5698x; 1.5698x over previous
#include <cuda_runtime.h>
#include <cuda_fp16.h>
#include <stdint.h>

#define Tlen 96
#define NTH  256

// Pre-swizzled fp16 tiles in device scratch (L2-resident).
// Wg : [cb][gate(r,z,n)][chunk<10] {64n x 64k}   (chunks 0-7 = w_hh k, 8-9 = w_ih k)
// Wf : [cb][chunk<8] {16n x 64k}
// Act: [buf][mb][hl][chunk<10] {128m x 64k}      (activation hi/lo pair; 0-7 = h, 8-9 = x)
__device__ __align__(16) __half d_Wg[8][3][10][4096];
__device__ __align__(16) __half d_Wf[8][8][1024];
__device__ __align__(16) __half d_Act[2][16][2][10][8192];
__device__ unsigned int d_bar;

// Tile layout: row-major rows of 64 fp16 (128B), 16B units xor-swizzled by row.
__host__ __device__ __forceinline__ int tile_off(int row, int kk) {
    int unit = (kk >> 3) ^ (row & 7);
    return row * 128 + (unit << 4) + (kk & 7) * 2;
}
__device__ __forceinline__ void hsplit(float f, __half& hi, __half& lo) {
    hi = __float2half(f);
    lo = __float2half(f - __half2float(hi));
}
__device__ __forceinline__ uint32_t smem_u32(const void* p) {
    uint32_t a;
    asm("{ .reg .u64 t; cvta.to.shared.u64 t, %1; cvt.u32.u64 %0, t; }" : "=r"(a) : "l"(p));
    return a;
}
__device__ __forceinline__ void cpa16(uint32_t dst, const void* src) {
    asm volatile("cp.async.cg.shared.global [%0], [%1], 16;" :: "r"(dst), "l"(src));
}
#define CP_COMMIT() asm volatile("cp.async.commit_group;" ::: "memory")
#define CP_WAIT1()  asm volatile("cp.async.wait_group 1;" ::: "memory")
#define CP_WAIT0()  asm volatile("cp.async.wait_group 0;" ::: "memory")

__device__ __forceinline__ void ldsm4(uint32_t* r, uint32_t a) {
    asm volatile("ldmatrix.sync.aligned.m8n8.x4.shared.b16 {%0,%1,%2,%3}, [%4];"
        : "=r"(r[0]), "=r"(r[1]), "=r"(r[2]), "=r"(r[3]) : "r"(a));
}
__device__ __forceinline__ void mmah(float* d, const uint32_t* a, const uint32_t* b) {
    asm volatile("mma.sync.aligned.m16n8k16.row.col.f32.f16.f16.f32 "
        "{%0,%1,%2,%3},{%4,%5,%6,%7},{%8,%9},{%0,%1,%2,%3};"
        : "+f"(d[0]), "+f"(d[1]), "+f"(d[2]), "+f"(d[3])
        : "r"(a[0]), "r"(a[1]), "r"(a[2]), "r"(a[3]), "r"(b[0]), "r"(b[1]));
}
// A fragment (m16 x k16) and B fragment (2 n8 tiles x k16) smem addresses
__device__ __forceinline__ uint32_t a_addr(uint32_t base, int mrow, int q, int lane) {
    int row = mrow + ((lane >> 3) & 1) * 8 + (lane & 7);
    int unit = 2 * q + (lane >> 4);
    return base + row * 128 + ((unit ^ (row & 7)) << 4);
}
__device__ __forceinline__ uint32_t b_addr(uint32_t base, int nbase, int q, int lane) {
    int nrow = nbase + ((lane >> 4) << 3) + (lane & 7);
    int unit = 2 * q + ((lane >> 3) & 1);
    return base + nrow * 128 + ((unit ^ (nrow & 7)) << 4);
}

__device__ __forceinline__ float sigm(float x) { return __fdividef(1.f, 1.f + __expf(-x)); }
__device__ __forceinline__ float ftanh(float x) {
    float t = __expf(2.f * x);
    return 1.f - __fdividef(2.f, t + 1.f);
}
__device__ __forceinline__ void grid_sync(unsigned tgt) {
    __threadfence();
    __syncthreads();
    if (threadIdx.x == 0) {
        atomicAdd(&d_bar, 1u);
        while (((volatile unsigned int*)&d_bar)[0] < tgt) __nanosleep(32);
    }
    __syncthreads();
    __threadfence();
}

// ---------------- setup kernels ----------------
__global__ void setup_weights(const float* __restrict__ w_ih,
                              const float* __restrict__ w_hh,
                              const float* __restrict__ fc_w) {
    const int N1 = 8 * 3 * 10 * 4096, N2 = 8 * 8 * 1024;
    for (int idx = blockIdx.x * blockDim.x + threadIdx.x; idx < N1 + N2;
         idx += gridDim.x * blockDim.x) {
        if (idx < N1) {
            int cb = idx / (3 * 10 * 4096), r = idx % (3 * 10 * 4096);
            int g = r / (10 * 4096); r %= 10 * 4096;
            int c = r / 4096, e = r % 4096;
            int j = e >> 6, kk = e & 63;
            int n = g * 512 + cb * 64 + j;
            float f = (c < 8) ? w_hh[n * 512 + c * 64 + kk]
                              : w_ih[n * 128 + (c - 8) * 64 + kk];
            *(__half*)((char*)&d_Wg[cb][g][c][0] + tile_off(j, kk)) = __float2half(f);
        } else {
            int i2 = idx - N1;
            int cb = i2 / (8 * 1024), r = i2 % (8 * 1024);
            int c = r / 1024, e = r % 1024;
            int j = e >> 6, kk = e & 63;
            float f = fc_w[(cb * 16 + j) * 512 + c * 64 + kk];
            *(__half*)((char*)&d_Wf[cb][c][0] + tile_off(j, kk)) = __float2half(f);
        }
    }
}

__global__ void setup_state(const float* __restrict__ hidden) {
    const int N1 = 2048 * 512, N2 = 16 * 2 * 2 * 8192;
    for (int idx = blockIdx.x * blockDim.x + threadIdx.x; idx < N1 + N2;
         idx += gridDim.x * blockDim.x) {
        if (idx < N1) {
            int row = idx >> 9, col = idx & 511;
            int mb = row >> 7, m = row & 127, c = col >> 6, kk = col & 63;
            __half hi, lo; hsplit(hidden[idx], hi, lo);
            int to = tile_off(m, kk);
            *(__half*)((char*)&d_Act[0][mb][0][c][0] + to) = hi;
            *(__half*)((char*)&d_Act[0][mb][1][c][0] + to) = lo;
        } else {
            int i2 = idx - N1;
            int mb = i2 / (2 * 2 * 8192), r = i2 % (2 * 2 * 8192);
            int hl = r / (2 * 8192); r %= 2 * 8192;
            int c8 = r / 8192, e = r % 8192;
            d_Act[0][mb][hl][8 + c8][e] = __float2half(0.f);
        }
    }
    if (blockIdx.x == 0 && threadIdx.x == 0) d_bar = 0;
}

// ---------------- main persistent kernel ----------------
// smem: [64..1216) biases; A bufs @2048 (2 x 32KB hi+lo); B bufs @67584 (2 x 24KB).
#define SM_A  2048
#define SM_B  67584
#define SMTOT 116736

// One gate's n32 slice for one k16: 2-product mma into acc[2][4][4].
__device__ __forceinline__ void process_gate(
    uint32_t Bg, int lane, int wn32, int q,
    const uint32_t ah[2][4], const uint32_t al[2][4], float (*acc)[4][4])
{
    uint32_t b0[4], b1[4];
    ldsm4(b0, b_addr(Bg, wn32, q, lane));        // tiles nt0, nt1
    ldsm4(b1, b_addr(Bg, wn32 + 16, q, lane));   // tiles nt2, nt3
    #pragma unroll
    for (int mb2 = 0; mb2 < 2; ++mb2) {
        mmah(acc[mb2][0], ah[mb2], b0);     mmah(acc[mb2][1], ah[mb2], b0 + 2);
        mmah(acc[mb2][2], ah[mb2], b1);     mmah(acc[mb2][3], ah[mb2], b1 + 2);
        mmah(acc[mb2][0], al[mb2], b0);     mmah(acc[mb2][1], al[mb2], b0 + 2);
        mmah(acc[mb2][2], al[mb2], b1);     mmah(acc[mb2][3], al[mb2], b1 + 2);
    }
}

__global__ __launch_bounds__(NTH, 1)
void gru_main(const float* __restrict__ b_ih, const float* __restrict__ b_hh,
              const float* __restrict__ fc_b, float* __restrict__ out) {
    extern __shared__ char sm[];
    const uint32_t smb = smem_u32(sm);
    const int tid = threadIdx.x;
    const int wid = tid >> 5, lane = tid & 31;
    const int mb = blockIdx.x >> 3, cb = blockIdx.x & 7;
    const int wm32 = (wid & 3) * 32;   // warp m-rows
    const int wn32 = (wid >> 2) * 32;  // warp gate-cols

    float* s_br = (float*)(sm + 64);
    float* s_bz = s_br + 64;
    float* s_bi = s_bz + 64;
    float* s_bh = s_bi + 64;
    float* s_fb = s_bh + 64;
    if (tid < 64) {
        s_br[tid] = b_ih[cb * 64 + tid] + b_hh[cb * 64 + tid];
        s_bz[tid] = b_ih[512 + cb * 64 + tid] + b_hh[512 + cb * 64 + tid];
        s_bi[tid] = b_ih[1024 + cb * 64 + tid];
        s_bh[tid] = b_hh[1024 + cb * 64 + tid];
    }
    if (tid < 16) s_fb[tid] = fc_b[cb * 16 + tid];
    __syncthreads();

    unsigned tgt = 0;

    for (int s = 0; s < Tlen; ++s) {
        const int cur = s & 1, nxt = cur ^ 1;

        // ===== gates: [128 x (r64|z64|n64)] over K=640, 10 chunks, dbl-buffered =====
        float aR[2][4][4], aZ[2][4][4], aN[2][4][4], aI[2][4][4];
        #pragma unroll
        for (int i = 0; i < 2; ++i)
            #pragma unroll
            for (int t = 0; t < 4; ++t)
                #pragma unroll
                for (int k = 0; k < 4; ++k) {
                    aR[i][t][k] = 0.f; aZ[i][t][k] = 0.f;
                    aN[i][t][k] = 0.f; aI[i][t][k] = 0.f;
                }

        #define STAGE_GATE(c, b) do {                                              \
            const char* Ah_ = (const char*)&d_Act[cur][mb][0][(c)][0];             \
            const char* Al_ = (const char*)&d_Act[cur][mb][1][(c)][0];             \
            uint32_t AB_ = smb + SM_A + (b) * 32768;                               \
            _Pragma("unroll")                                                      \
            for (int r_ = 0; r_ < 4; ++r_) {                                       \
                int u_ = tid + r_ * NTH;                                           \
                cpa16(AB_ + u_ * 16, Ah_ + u_ * 16);                               \
                cpa16(AB_ + 16384 + u_ * 16, Al_ + u_ * 16);                       \
            }                                                                      \
            uint32_t BB_ = smb + SM_B + (b) * 24576;                               \
            _Pragma("unroll")                                                      \
            for (int r_ = 0; r_ < 6; ++r_) {                                       \
                int u_ = tid + r_ * NTH;           /* 0..1535 */                   \
                int g_ = u_ >> 9, e_ = u_ & 511;                                   \
                const char* src_ = (const char*)&d_Wg[cb][g_][(c)][0];             \
                cpa16(BB_ + g_ * 8192 + e_ * 16, src_ + e_ * 16);                  \
            }                                                                      \
        } while (0)

        STAGE_GATE(0, 0);
        CP_COMMIT();
        #pragma unroll 1
        for (int c = 0; c < 10; ++c) {
            if (c < 9) { STAGE_GATE(c + 1, (c + 1) & 1); CP_COMMIT(); CP_WAIT1(); }
            else       { CP_WAIT0(); }
            __syncthreads();
            const uint32_t AB = smb + SM_A + (c & 1) * 32768;
            const uint32_t BB = smb + SM_B + (c & 1) * 24576;
            float (*aX)[4][4] = (c < 8) ? aN : aI;
            #pragma unroll
            for (int q = 0; q < 4; ++q) {
                uint32_t ah[2][4], al[2][4];
                ldsm4(ah[0], a_addr(AB, wm32, q, lane));
                ldsm4(ah[1], a_addr(AB, wm32 + 16, q, lane));
                ldsm4(al[0], a_addr(AB + 16384, wm32, q, lane));
                ldsm4(al[1], a_addr(AB + 16384, wm32 + 16, q, lane));
                process_gate(BB,         lane, wn32, q, ah, al, aR);
                process_gate(BB + 8192,  lane, wn32, q, ah, al, aZ);
                process_gate(BB + 16384, lane, wn32, q, ah, al, aX);
            }
            __syncthreads();
        }

        // ===== gates epilogue: h_new for cols cb*64 + [0,64) (register-local) =====
        {
            const char* hiC = (const char*)&d_Act[cur][mb][0][cb][0];
            const char* loC = (const char*)&d_Act[cur][mb][1][cb][0];
            char* hiN = (char*)&d_Act[nxt][mb][0][cb][0];
            char* loN = (char*)&d_Act[nxt][mb][1][cb][0];
            #pragma unroll
            for (int mb2 = 0; mb2 < 2; ++mb2)
                #pragma unroll
                for (int nt = 0; nt < 4; ++nt) {
                    const int jj = wn32 + nt * 8 + 2 * (lane & 3);
                    #pragma unroll
                    for (int ms = 0; ms < 2; ++ms) {
                        const int m_ = wm32 + mb2 * 16 + (lane >> 2) + ms * 8;
                        const int eo = tile_off(m_, jj);
                        __half2 oh = *(const __half2*)(hiC + eo);
                        __half2 ol = *(const __half2*)(loC + eo);
                        float hp0 = __half2float(oh.x) + __half2float(ol.x);
                        float hp1 = __half2float(oh.y) + __half2float(ol.y);
                        float r0 = sigm(aR[mb2][nt][ms * 2]     + s_br[jj]);
                        float r1 = sigm(aR[mb2][nt][ms * 2 + 1] + s_br[jj + 1]);
                        float z0 = sigm(aZ[mb2][nt][ms * 2]     + s_bz[jj]);
                        float z1 = sigm(aZ[mb2][nt][ms * 2 + 1] + s_bz[jj + 1]);
                        float n0 = ftanh(aI[mb2][nt][ms * 2]     + s_bi[jj] +
                                         r0 * (aN[mb2][nt][ms * 2]     + s_bh[jj]));
                        float n1 = ftanh(aI[mb2][nt][ms * 2 + 1] + s_bi[jj + 1] +
                                         r1 * (aN[mb2][nt][ms * 2 + 1] + s_bh[jj + 1]));
                        float h0 = (1.f - z0) * n0 + z0 * hp0;
                        float h1 = (1.f - z1) * n1 + z1 * hp1;
                        __half q0, l0, q1, l1;
                        hsplit(h0, q0, l0); hsplit(h1, q1, l1);
                        __half2 vh; vh.x = q0; vh.y = q1;
                        __half2 vl; vl.x = l0; vl.y = l1;
                        *(__half2*)(hiN + eo) = vh;
                        *(__half2*)(loN + eo) = vl;
                    }
                }
        }
        tgt += 128;
        grid_sync(tgt);   // all h_new tiles visible

        // ===== fc: [128 x 16] over K=512 (h_new), 8 chunks, dbl-buffered =====
        float f0[2][4];
        #pragma unroll
        for (int t = 0; t < 2; ++t)
            #pragma unroll
            for (int k = 0; k < 4; ++k) f0[t][k] = 0.f;

        #define STAGE_FC(c, b) do {                                                \
            const char* Ah_ = (const char*)&d_Act[nxt][mb][0][(c)][0];             \
            const char* Al_ = (const char*)&d_Act[nxt][mb][1][(c)][0];             \
            uint32_t AB_ = smb + SM_A + (b) * 32768;                               \
            _Pragma("unroll")                                                      \
            for (int r_ = 0; r_ < 4; ++r_) {                                       \
                int u_ = tid + r_ * NTH;                                           \
                cpa16(AB_ + u_ * 16, Ah_ + u_ * 16);                               \
                cpa16(AB_ + 16384 + u_ * 16, Al_ + u_ * 16);                       \
            }                                                                      \
            uint32_t BB_ = smb + SM_B + (b) * 24576;                               \
            if (tid < 128) {                                                       \
                const char* src_ = (const char*)&d_Wf[cb][(c)][0];                 \
                cpa16(BB_ + tid * 16, src_ + tid * 16);                            \
            }                                                                      \
        } while (0)

        STAGE_FC(0, 0);
        CP_COMMIT();
        #pragma unroll 1
        for (int c = 0; c < 8; ++c) {
            if (c < 7) { STAGE_FC(c + 1, (c + 1) & 1); CP_COMMIT(); CP_WAIT1(); }
            else       { CP_WAIT0(); }
            __syncthreads();
            const uint32_t AB = smb + SM_A + (c & 1) * 32768;
            const uint32_t BB = smb + SM_B + (c & 1) * 24576;
            #pragma unroll
            for (int q = 0; q < 4; ++q) {
                uint32_t ah[4], al[4], bb[4];
                ldsm4(ah, a_addr(AB, wid * 16, q, lane));
                ldsm4(al, a_addr(AB + 16384, wid * 16, q, lane));
                ldsm4(bb, b_addr(BB, 0, q, lane));          // 2 n8 tiles
                mmah(f0[0], ah, bb); mmah(f0[1], ah, bb + 2);
                mmah(f0[0], al, bb); mmah(f0[1], al, bb + 2);
            }
            __syncthreads();
        }

        // ===== fc epilogue: x_new cols cb*16+[0,16) -> out + x tiles =====
        {
            const int trow = Tlen - 1 - s;   // reference reverses time at the end
            const int xc = 8 + (cb >> 2);
            char* xhi = (char*)&d_Act[nxt][mb][0][xc][0];
            char* xlo = (char*)&d_Act[nxt][mb][1][xc][0];
            #pragma unroll
            for (int nt = 0; nt < 2; ++nt) {
                const int col = nt * 8 + 2 * (lane & 3);
                #pragma unroll
                for (int ms = 0; ms < 2; ++ms) {
                    const int m_ = wid * 16 + (lane >> 2) + ms * 8;
                    float x0 = f0[nt][ms * 2]     + s_fb[col];
                    float x1 = f0[nt][ms * 2 + 1] + s_fb[col + 1];
                    *(float2*)&out[((size_t)(mb * 128 + m_) * Tlen + trow) * 128 +
                                   cb * 16 + col] = make_float2(x0, x1);
                    const int kk = (cb & 3) * 16 + col;
                    const int eo = tile_off(m_, kk);
                    __half q0, l0, q1, l1;
                    hsplit(x0, q0, l0); hsplit(x1, q1, l1);
                    __half2 vh; vh.x = q0; vh.y = q1;
                    __half2 vl; vl.x = l0; vl.y = l1;
                    *(__half2*)(xhi + eo) = vh;
                    *(__half2*)(xlo + eo) = vl;
                }
            }
        }
        tgt += 128;
        grid_sync(tgt);   // x tiles visible before next step
    }
}

extern "C" void kernel_launch(void* const* d_in, const int* in_sizes, int n_in,
                              void* d_out, int out_size) {
    const float* hidden = (const float*)d_in[0];
    const float* w_ih   = (const float*)d_in[1];
    const float* w_hh   = (const float*)d_in[2];
    const float* b_ih   = (const float*)d_in[3];
    const float* b_hh   = (const float*)d_in[4];
    const float* fc_w   = (const float*)d_in[5];
    const float* fc_b   = (const float*)d_in[6];
    float* out = (float*)d_out;

    setup_weights<<<1024, 256>>>(w_ih, w_hh, fc_w);
    setup_state<<<1024, 256>>>(hidden);

    cudaFuncSetAttribute(gru_main, cudaFuncAttributeMaxDynamicSharedMemorySize, SMTOT);
    gru_main<<<128, NTH, SMTOT>>>(b_ih, b_hh, fc_b, out);
}